// round 7
// baseline (speedup 1.0000x reference)
#include <cuda_runtime.h>

#define N_ROWS    65536
#define N_CLASSES 1000
#define N_F4      250          // 1000 / 4
#define EPS_F     1e-9f
#define NORM_FAC  0.1f
#define WARPS_PER_BLOCK 8
#define N_BLOCKS  (N_ROWS / WARPS_PER_BLOCK)   // 8192

__device__ float        g_acc   = 0.0f;
__device__ unsigned int g_count = 0;

__global__ __launch_bounds__(WARPS_PER_BLOCK * 32)
void cosine_loss_kernel(const float* __restrict__ pred,
                        const long long* __restrict__ target,
                        float* __restrict__ out) {
    const int warp = threadIdx.x >> 5;
    const int lane = threadIdx.x & 31;
    const int row  = blockIdx.x * WARPS_PER_BLOCK + warp;

    const float4* __restrict__ rowp =
        reinterpret_cast<const float4*>(pred + (size_t)row * N_CLASSES);

    const int t = (int)target[row];
    const int t_f4   = t >> 2;
    const int t_comp = t & 3;

    // Front-batch ALL 8 loads (MLP=8). Out-of-range lanes (j==7, lane>=26)
    // clamp to index 249 — same sector as lane 25's load, no extra traffic.
    float4 v[8];
    #pragma unroll
    for (int j = 0; j < 8; j++) {
        const int f4  = lane + 32 * j;
        const int f4c = min(f4, N_F4 - 1);
        v[j] = __ldcs(rowp + f4c);
    }

    float sumsq    = 0.0f;
    float gathered = 0.0f;

    #pragma unroll
    for (int j = 0; j < 8; j++) {
        const int f4 = lane + 32 * j;
        const float4 w = v[j];
        if (f4 < N_F4) {
            sumsq += w.x * w.x + w.y * w.y + w.z * w.z + w.w * w.w;
        }
        if (f4 == t_f4) {
            gathered = (t_comp == 0) ? w.x :
                       (t_comp == 1) ? w.y :
                       (t_comp == 2) ? w.z : w.w;
        }
    }

    #pragma unroll
    for (int off = 16; off > 0; off >>= 1) {
        sumsq    += __shfl_xor_sync(0xffffffffu, sumsq, off);
        gathered += __shfl_xor_sync(0xffffffffu, gathered, off);
    }

    __shared__ float s_partial[WARPS_PER_BLOCK];
    if (lane == 0) {
        const float norm = sqrtf(sumsq);
        const float d    = 1.0f - norm;
        s_partial[warp] = (-gathered / (norm + EPS_F) + NORM_FAC * d * d)
                          * (1.0f / (float)N_ROWS);
    }
    __syncthreads();

    if (threadIdx.x == 0) {
        float acc = 0.0f;
        #pragma unroll
        for (int i = 0; i < WARPS_PER_BLOCK; i++) acc += s_partial[i];
        atomicAdd(&g_acc, acc);

        // acq_rel atomic on the counter: release orders this block's g_acc
        // add before the counter bump (no pipeline-draining MEMBAR.GPU);
        // acquire makes all other blocks' g_acc adds visible to the last
        // block. Replaces __threadfence().
        unsigned int old;
        asm volatile("atom.acq_rel.gpu.global.add.u32 %0, [%1], %2;"
                     : "=r"(old)
                     : "l"(&g_count), "r"(1u)
                     : "memory");

        if (old == (unsigned int)(N_BLOCKS - 1)) {
            // last block: publish result and reset globals for graph replay.
            *out    = g_acc;
            g_acc   = 0.0f;
            g_count = 0;
        }
    }
}

extern "C" void kernel_launch(void* const* d_in, const int* in_sizes, int n_in,
                              void* d_out, int out_size) {
    const float*     pred   = (const float*)d_in[0];
    const long long* target = (const long long*)d_in[1];
    float*           out    = (float*)d_out;

    cosine_loss_kernel<<<N_BLOCKS, WARPS_PER_BLOCK * 32>>>(pred, target, out);
}